// round 17
// baseline (speedup 1.0000x reference)
#include <cuda_runtime.h>
#include <cstdint>

#define DINLINE __device__ __forceinline__

typedef unsigned long long u64;

namespace {
constexpr int L = 160, H = 128, HP = 129, R = 4, BATCH = 2, D = 768;
constexpr int NKJ = H * HP;                              // 16512
constexpr long long WTRI_R = (long long)HP * NKJ;        // 2130048

constexpr long long ARENA_SZ = (long long)BATCH * R * L * H * L;  // W2 only
constexpr long long W2_B = (long long)R * L * H * L;     // per-b W2 floats

constexpr int SM_160_128 = (2 * 32 * 164 + 2 * 32 * 128) * 4;  // 74752
constexpr int SM_128_160 = (2 * 32 * 132 + 2 * 32 * 160) * 4;  // 74752
// fused kernel: As3[160][84] | Bs3[2][32][128] | red[80][20]
constexpr int F8_AS3 = 160 * 84;            // 13440 floats
constexpr int F8_BS3 = 2 * 32 * 128;        // 8192
constexpr int F8_RED = 80 * 20;             // 1600
constexpr int SM_F8 = (F8_AS3 + F8_BS3 + F8_RED) * 4;  // 92928 bytes
}

// ------------------------- static device scratch ----------------------------
__device__ float g_hidden[BATCH * L * 4 * H];    // [b*L+l][512]
__device__ float g_scoring[BATCH * L * 2 * H];   // [b*L+l][256]
__device__ float g_inPT[BATCH * HP * L];         // [b][j][z], row j=128 -> 1
__device__ float g_xtailPT[BATCH * HP * L];      // [b][m][y], row m=128 -> 1
__device__ float g_U[(long long)BATCH * R * L * NKJ];   // [(b*R+r)*L+y][k*129+j]
__device__ float g_G[(long long)BATCH * L * NKJ];       // [b][x][q*129+m]
__device__ float g_Gt2[(long long)BATCH * L * H * L];   // [b][x*128+q][y]
__device__ float g_Gt3[(long long)BATCH * L * L * H];   // [b][y][x*128+q]
__device__ float g_HRW[BATCH * L * H];                  // [b][z][q]
__device__ float g_arena[ARENA_SZ];                     // W2 [b][(r,y)][k][z]

DINLINE float leaky(float v) { return v >= 0.f ? v : 0.1f * v; }

// ---- packed dual-FMA helpers (FFMA2 via PTX f32x2; sm_100+) ----------------
DINLINE u64 pack2(float x, float y) {
  u64 r;
  asm("mov.b64 %0, {%1, %2};" : "=l"(r) : "f"(x), "f"(y));
  return r;
}
DINLINE void unpack2(u64 v, float& x, float& y) {
  asm("mov.b64 {%0, %1}, %2;" : "=f"(x), "=f"(y) : "l"(v));
}
DINLINE void fma2(u64& acc, u64 a, u64 b) {
  asm("fma.rn.f32x2 %0, %1, %2, %0;" : "+l"(acc) : "l"(a), "l"(b));
}

// ---- cp.async helpers ------------------------------------------------------
DINLINE void cp4(uint32_t dst, const float* src) {
  asm volatile("cp.async.ca.shared.global [%0], [%1], 4;"
               :: "r"(dst), "l"(src));
}
DINLINE void cp16(uint32_t dst, const float* src) {
  asm volatile("cp.async.cg.shared.global [%0], [%1], 16;"
               :: "r"(dst), "l"(src));
}
#define CP_COMMIT() asm volatile("cp.async.commit_group;" ::: "memory")
#define CP_WAIT0()  asm volatile("cp.async.wait_group 0;" ::: "memory")

// ---- cp.async double-buffered GEMM, BK=32, 8x8 microtile, FFMA2 -------------
// Batched over blockIdx.z: bz = z / ZD, rz = z % ZD.
// ep: 0 none | 1 leaky(acc+bias[n]) | 2 acc+B[K][n] | 3 acc+A[m][K]
template <int BM, int BN, int OCC>
__global__ void __launch_bounds__((BM / 8) * (BN / 8), OCC) gemm6(
    const float* __restrict__ A, const float* __restrict__ B,
    float* __restrict__ C, int M, int N, int K, int lda, int ldb, int ldc,
    long long sA, long long sA2, long long sB, long long sB2, long long sC,
    int ZD, int ep, const float* __restrict__ bias) {
  constexpr int NT = (BM / 8) * (BN / 8);
  constexpr int AST = BM + 4;
  constexpr int AR = (BM * 32 + NT - 1) / NT;
  constexpr int BR = (BN * 8 + NT - 1) / NT;
  extern __shared__ float smem[];
  float* As = smem;                 // [2][32][AST]
  float* Bs = smem + 2 * 32 * AST;  // [2][32][BN]
  const int z = blockIdx.z;
  const int bz = z / ZD, rz = z % ZD;
  A += bz * sA + rz * sA2;
  B += bz * sB + rz * sB2;
  C += (long long)z * sC;
  const int tid = threadIdx.x;
  const int tx = tid % (BN / 8), ty = tid / (BN / 8);
  const int m0 = blockIdx.y * BM, n0 = blockIdx.x * BN;

  const uint32_t sbA = (uint32_t)__cvta_generic_to_shared(As);
  const uint32_t sbB = (uint32_t)__cvta_generic_to_shared(Bs);

  auto prefetch = [&](int k0, int s) {
#pragma unroll
    for (int t = 0; t < AR; ++t) {
      int idx = tid + t * NT;
      if (idx < BM * 32) {
        int m = idx >> 5, k = idx & 31;
        cp4(sbA + (((s * 32 + k) * AST + m) << 2),
            A + (long long)(m0 + m) * lda + k0 + k);
      }
    }
#pragma unroll
    for (int t = 0; t < BR; ++t) {
      int idx = tid + t * NT;
      if (idx < BN * 8) {
        int k = idx / (BN / 4), n4 = idx % (BN / 4);
        cp16(sbB + (((s * 32 + k) * BN + n4 * 4) << 2),
             B + (long long)(k0 + k) * ldb + n0 + n4 * 4);
      }
    }
  };

  u64 acc2[8][4] = {};
  prefetch(0, 0);
  CP_COMMIT();
  int buf = 0;
  for (int k0 = 0; k0 < K; k0 += 32) {
    CP_WAIT0();
    __syncthreads();
    const bool next = (k0 + 32) < K;
    if (next) {
      prefetch(k0 + 32, buf ^ 1);
      CP_COMMIT();
    }
    const float* Ab = As + buf * 32 * AST;
    const float* Bb = Bs + buf * 32 * BN;
#pragma unroll 16
    for (int k = 0; k < 32; ++k) {
      float4 A0 = *(const float4*)(Ab + k * AST + ty * 4);
      float4 A1 = *(const float4*)(Ab + k * AST + BM / 2 + ty * 4);
      ulonglong2 B0 = *(const ulonglong2*)(Bb + k * BN + tx * 4);
      ulonglong2 B1 = *(const ulonglong2*)(Bb + k * BN + BN / 2 + tx * 4);
      u64 a2[8];
      a2[0] = pack2(A0.x, A0.x); a2[1] = pack2(A0.y, A0.y);
      a2[2] = pack2(A0.z, A0.z); a2[3] = pack2(A0.w, A0.w);
      a2[4] = pack2(A1.x, A1.x); a2[5] = pack2(A1.y, A1.y);
      a2[6] = pack2(A1.z, A1.z); a2[7] = pack2(A1.w, A1.w);
#pragma unroll
      for (int i = 0; i < 8; ++i) {
        fma2(acc2[i][0], a2[i], B0.x);
        fma2(acc2[i][1], a2[i], B0.y);
        fma2(acc2[i][2], a2[i], B1.x);
        fma2(acc2[i][3], a2[i], B1.y);
      }
    }
    buf ^= 1;
  }
  float acc[8][8];
#pragma unroll
  for (int i = 0; i < 8; ++i) {
    unpack2(acc2[i][0], acc[i][0], acc[i][1]);
    unpack2(acc2[i][1], acc[i][2], acc[i][3]);
    unpack2(acc2[i][2], acc[i][4], acc[i][5]);
    unpack2(acc2[i][3], acc[i][6], acc[i][7]);
  }
  float4 br0 = make_float4(0.f, 0.f, 0.f, 0.f), br1 = br0;
  if (ep == 2) {
    const float* Brow = B + (long long)K * ldb;
    br0 = *(const float4*)(Brow + n0 + tx * 4);
    br1 = *(const float4*)(Brow + n0 + BN / 2 + tx * 4);
  }
#pragma unroll
  for (int i = 0; i < 8; ++i) {
    int m = m0 + (i < 4 ? ty * 4 + i : BM / 2 + ty * 4 + (i - 4));
    float ra = (ep == 3) ? A[(long long)m * lda + K] : 0.f;
#pragma unroll
    for (int jh = 0; jh < 2; ++jh) {
      int n = n0 + (jh ? BN / 2 : 0) + tx * 4;
      float4 v = make_float4(acc[i][jh * 4 + 0], acc[i][jh * 4 + 1],
                             acc[i][jh * 4 + 2], acc[i][jh * 4 + 3]);
      if (ep == 1) {
        v.x = leaky(v.x + bias[n + 0]);
        v.y = leaky(v.y + bias[n + 1]);
        v.z = leaky(v.z + bias[n + 2]);
        v.w = leaky(v.w + bias[n + 3]);
      } else if (ep == 2) {
        float4 br = jh ? br1 : br0;
        v.x += br.x; v.y += br.y; v.z += br.z; v.w += br.w;
      } else if (ep == 3) {
        v.x += ra; v.y += ra; v.z += ra; v.w += ra;
      }
      *(float4*)(C + (long long)m * ldc + n) = v;
    }
  }
}

// ---- fused logits -> softmax -> SP -> score per (b,r,y) x-half --------------
// grid (1, 2, BATCH*R*L), 200 threads. (Audited R13 design.)
__global__ void __launch_bounds__(200, 2) k_fused8(
    const float* __restrict__ head, const float* __restrict__ W2,
    const float* __restrict__ HRW, const float* __restrict__ Gt3,
    const float* __restrict__ bmlp, float* __restrict__ out) {
  extern __shared__ float smem[];
  float* As1 = smem;                       // [2][32][84]
  float* Bs1 = smem + 2 * 32 * 84;         // [2][32][160]
  float* As3 = smem;                       // [160][84]  (overlays phase1)
  float* Bs3 = smem + F8_AS3;              // [2][32][128]
  float* red = smem + F8_AS3 + F8_BS3;     // [80][20]
  const int z = blockIdx.z;
  const int bz = z / (R * L), rz = z % (R * L);
  const int r = rz / L, y = rz % L;
  const int m0 = blockIdx.y * 80;
  const int tid = threadIdx.x;
  const int tx = tid % 20, ty = tid / 20;  // phase1/2: 20 cols x 10 rows

  const float* A = head + (long long)bz * L * 512;       // lda=512
  const float* B = W2 + (long long)z * (H * L);          // [128][160]

  const uint32_t sbA = (uint32_t)__cvta_generic_to_shared(As1);
  const uint32_t sbB = (uint32_t)__cvta_generic_to_shared(Bs1);
  const uint32_t sbB3 = (uint32_t)__cvta_generic_to_shared(Bs3);

  // ---------------- phase 1: logits GEMM (K=128) ----------------
  auto prefetch1 = [&](int k0, int s) {
#pragma unroll
    for (int t = 0; t < 13; ++t) {
      int idx = tid + t * 200;
      if (idx < 80 * 32) {
        int m = idx >> 5, k = idx & 31;
        cp4(sbA + (((s * 32 + k) * 84 + m) << 2),
            A + (long long)(m0 + m) * 512 + k0 + k);
      }
    }
#pragma unroll
    for (int t = 0; t < 7; ++t) {
      int idx = tid + t * 200;
      if (idx < 160 * 8) {
        int k = idx / 40, n4 = idx % 40;
        cp16(sbB + (((s * 32 + k) * 160 + n4 * 4) << 2),
             B + (long long)(k0 + k) * 160 + n4 * 4);
      }
    }
  };
  float acc[8][8] = {};
  prefetch1(0, 0);
  CP_COMMIT();
  int buf = 0;
  for (int k0 = 0; k0 < 128; k0 += 32) {
    CP_WAIT0();
    __syncthreads();
    if (k0 + 32 < 128) {
      prefetch1(k0 + 32, buf ^ 1);
      CP_COMMIT();
    }
    const float* Ab = As1 + buf * 32 * 84;
    const float* Bb = Bs1 + buf * 32 * 160;
#pragma unroll 16
    for (int k = 0; k < 32; ++k) {
      float4 A0 = *(const float4*)(Ab + k * 84 + ty * 4);
      float4 A1 = *(const float4*)(Ab + k * 84 + 40 + ty * 4);
      float4 B0 = *(const float4*)(Bb + k * 160 + tx * 4);
      float4 B1 = *(const float4*)(Bb + k * 160 + 80 + tx * 4);
      float av[8] = {A0.x, A0.y, A0.z, A0.w, A1.x, A1.y, A1.z, A1.w};
      float bv[8] = {B0.x, B0.y, B0.z, B0.w, B1.x, B1.y, B1.z, B1.w};
#pragma unroll
      for (int i = 0; i < 8; ++i)
#pragma unroll
        for (int j = 0; j < 8; ++j)
          acc[i][j] = fmaf(av[i], bv[j], acc[i][j]);
    }
    buf ^= 1;
  }
  // ---------------- phase 2: softmax over z (in regs) ----------------
  int mloc[8];
#pragma unroll
  for (int i = 0; i < 8; ++i)
    mloc[i] = (i < 4 ? ty * 4 + i : 40 + ty * 4 + (i - 4));
#pragma unroll
  for (int i = 0; i < 8; ++i) {
    float lm = acc[i][0];
#pragma unroll
    for (int j = 1; j < 8; ++j) lm = fmaxf(lm, acc[i][j]);
    red[mloc[i] * 20 + tx] = lm;
  }
  __syncthreads();
  float mx[8];
#pragma unroll
  for (int i = 0; i < 8; ++i) {
    float m_ = red[mloc[i] * 20];
#pragma unroll
    for (int j = 1; j < 20; ++j) m_ = fmaxf(m_, red[mloc[i] * 20 + j]);
    mx[i] = m_;
  }
  __syncthreads();
#pragma unroll
  for (int i = 0; i < 8; ++i) {
    float ls = 0.f;
#pragma unroll
    for (int j = 0; j < 8; ++j) {
      acc[i][j] = __expf(acc[i][j] - mx[i]);
      ls += acc[i][j];
    }
    red[mloc[i] * 20 + tx] = ls;
  }
  __syncthreads();
#pragma unroll
  for (int i = 0; i < 8; ++i) {
    float s_ = 0.f;
#pragma unroll
    for (int j = 0; j < 20; ++j) s_ += red[mloc[i] * 20 + j];
    float inv = 1.f / s_;
#pragma unroll
    for (int j = 0; j < 8; ++j) acc[i][j] *= inv;
  }
  __syncthreads();  // phase-1 smem fully consumed; safe to overlay As3
#pragma unroll
  for (int i = 0; i < 8; ++i) {
#pragma unroll
    for (int jj = 0; jj < 4; ++jj) {
      As3[(tx * 4 + jj) * 84 + mloc[i]] = acc[i][jj];
      As3[(80 + tx * 4 + jj) * 84 + mloc[i]] = acc[i][jj + 4];
    }
  }
  // ---------------- phase 3: SP = alpha @ HRW (K=160) ----------------
  const float* B3 = HRW + (long long)bz * L * H;  // [160][128]
  auto prefetch3 = [&](int k0, int s) {
#pragma unroll
    for (int t = 0; t < 6; ++t) {
      int idx = tid + t * 200;
      if (idx < 32 * 32) {
        int k = idx >> 5, n4 = idx & 31;
        cp16(sbB3 + (((s * 32 + k) * 128 + n4 * 4) << 2),
             B3 + (long long)(k0 + k) * 128 + n4 * 4);
      }
    }
  };
  const int tx3 = tid % 16, ty3 = tid / 16;  // valid when tid < 160
  const bool act = tid < 160;
  float acc3[8][8] = {};
  prefetch3(0, 0);
  CP_COMMIT();
  buf = 0;
  for (int k0 = 0; k0 < 160; k0 += 32) {
    CP_WAIT0();
    __syncthreads();  // first iter also fences the As3 writes above
    if (k0 + 32 < 160) {
      prefetch3(k0 + 32, buf ^ 1);
      CP_COMMIT();
    }
    if (act) {
      const float* Bb = Bs3 + buf * 32 * 128;
#pragma unroll 16
      for (int k = 0; k < 32; ++k) {
        float4 A0 = *(const float4*)(As3 + (k0 + k) * 84 + ty3 * 4);
        float4 A1 = *(const float4*)(As3 + (k0 + k) * 84 + 40 + ty3 * 4);
        float4 B0 = *(const float4*)(Bb + k * 128 + tx3 * 4);
        float4 B1 = *(const float4*)(Bb + k * 128 + 64 + tx3 * 4);
        float av[8] = {A0.x, A0.y, A0.z, A0.w, A1.x, A1.y, A1.z, A1.w};
        float bv[8] = {B0.x, B0.y, B0.z, B0.w, B1.x, B1.y, B1.z, B1.w};
#pragma unroll
        for (int i = 0; i < 8; ++i)
#pragma unroll
          for (int j = 0; j < 8; ++j)
            acc3[i][j] = fmaf(av[i], bv[j], acc3[i][j]);
      }
    }
    buf ^= 1;
  }
  // ---------------- phase 4: leaky + score dot + reduce ----------------
  if (act) {
    float4 bb0 = *(const float4*)(bmlp + tx3 * 4);
    float4 bb1 = *(const float4*)(bmlp + 64 + tx3 * 4);
    const float* gbase = Gt3 + ((long long)(bz * L + y) * L) * H;
#pragma unroll
    for (int i = 0; i < 8; ++i) {
      int m = m0 + (i < 4 ? ty3 * 4 + i : 40 + ty3 * 4 + (i - 4));
      float4 g0 = *(const float4*)(gbase + (long long)m * H + tx3 * 4);
      float4 g1 = *(const float4*)(gbase + (long long)m * H + 64 + tx3 * 4);
      float s = leaky(acc3[i][0] + bb0.x) * g0.x +
                leaky(acc3[i][1] + bb0.y) * g0.y +
                leaky(acc3[i][2] + bb0.z) * g0.z +
                leaky(acc3[i][3] + bb0.w) * g0.w +
                leaky(acc3[i][4] + bb1.x) * g1.x +
                leaky(acc3[i][5] + bb1.y) * g1.y +
                leaky(acc3[i][6] + bb1.z) * g1.z +
                leaky(acc3[i][7] + bb1.w) * g1.w;
#pragma unroll
      for (int o = 8; o; o >>= 1) s += __shfl_xor_sync(0xffffffffu, s, o);
      if (tx3 == 0)
        out[((long long)((bz * R + r) * L + m)) * L + y] = s;
    }
  }
}

// ---------------- prep: inPT / xtailPT transposes ---------------------------
__global__ void k_prep2() {
  int t = blockIdx.x * blockDim.x + threadIdx.x;
  const int NPAD = BATCH * HP * L;  // 41280
  if (t < NPAD) {
    int b = t / (HP * L), rem = t % (HP * L);
    int j = rem / L, zz = rem % L;
    g_inPT[t] = (j < H)
        ? g_hidden[(long long)(b * L + zz) * (4 * H) + 3 * H + j] : 1.f;
    return;
  }
  t -= NPAD;
  if (t < NPAD) {
    int b = t / (HP * L), rem = t % (HP * L);
    int m = rem / L, y = rem % L;
    g_xtailPT[t] = (m < H)
        ? g_scoring[(long long)(b * L + y) * (2 * H) + H + m] : 1.f;
  }
}

// ---------------- Gt2[b][xq][y] -> Gt3[b][y][xq] (tiled transpose) ----------
__global__ void k_transpose(const float* __restrict__ in,
                            float* __restrict__ outp) {
  __shared__ float t[32][33];
  int b = blockIdx.z;
  int xq0 = blockIdx.x * 32, y0 = blockIdx.y * 32;
  const float* ip = in + (long long)b * (L * H) * L;
  float* op = outp + (long long)b * L * (L * H);
  int tx = threadIdx.x, ty0 = threadIdx.y;  // 32 x 8
  for (int i = ty0; i < 32; i += 8)
    t[i][tx] = ip[(long long)(xq0 + i) * L + (y0 + tx)];
  __syncthreads();
  for (int i = ty0; i < 32; i += 8)
    op[(long long)(y0 + i) * (L * H) + (xq0 + tx)] = t[tx][i];
}

// ------------------------------- launch --------------------------------------
static const float* pick_by_size(void* const* d_in, const int* in_sizes,
                                 int n_in, int want, int fallback_idx) {
  for (int i = 0; i < n_in; ++i)
    if (in_sizes[i] == want) return (const float*)d_in[i];
  return (const float*)d_in[fallback_idx];
}

extern "C" void kernel_launch(void* const* d_in, const int* in_sizes, int n_in,
                              void* d_out, int out_size) {
  (void)out_size;
  const float* x      = pick_by_size(d_in, in_sizes, n_in, BATCH * L * D, 0);
  const float* Wspan  = pick_by_size(d_in, in_sizes, n_in, D * 4 * H, 1);
  const float* bspan  = pick_by_size(d_in, in_sizes, n_in, 4 * H, 2);
  const float* Wscore = pick_by_size(d_in, in_sizes, n_in, D * 2 * H, 3);
  const float* bscore = pick_by_size(d_in, in_sizes, n_in, 2 * H, 4);
  const float* Wtri   = pick_by_size(d_in, in_sizes, n_in, R * HP * H * HP, 5);
  const float* Wmlp   = pick_by_size(d_in, in_sizes, n_in, H * H, 6);
  const float* bmlp   = pick_by_size(d_in, in_sizes, n_in, H, 7);
  const float* Wfin   = pick_by_size(d_in, in_sizes, n_in, HP * H * HP, 8);
  float* out = (float*)d_out;

  float* d_hidden;  cudaGetSymbolAddress((void**)&d_hidden, g_hidden);
  float* d_scoring; cudaGetSymbolAddress((void**)&d_scoring, g_scoring);
  float* d_inPT;    cudaGetSymbolAddress((void**)&d_inPT, g_inPT);
  float* d_xtailPT; cudaGetSymbolAddress((void**)&d_xtailPT, g_xtailPT);
  float* d_U;       cudaGetSymbolAddress((void**)&d_U, g_U);
  float* d_G;       cudaGetSymbolAddress((void**)&d_G, g_G);
  float* d_Gt2;     cudaGetSymbolAddress((void**)&d_Gt2, g_Gt2);
  float* d_Gt3;     cudaGetSymbolAddress((void**)&d_Gt3, g_Gt3);
  float* d_HRW;     cudaGetSymbolAddress((void**)&d_HRW, g_HRW);
  float* d_W2;      cudaGetSymbolAddress((void**)&d_W2, g_arena);

  cudaFuncSetAttribute(gemm6<160, 128, 2>,
                       cudaFuncAttributeMaxDynamicSharedMemorySize, SM_160_128);
  cudaFuncSetAttribute(gemm6<128, 160, 2>,
                       cudaFuncAttributeMaxDynamicSharedMemorySize, SM_128_160);
  cudaFuncSetAttribute(k_fused8,
                       cudaFuncAttributeMaxDynamicSharedMemorySize, SM_F8);

  // 1) hidden = leaky(x @ Wspan + bspan)   [320,512], K=768
  gemm6<160, 128, 2><<<dim3(4, 2, 1), 320, SM_160_128>>>(
      x, Wspan, d_hidden, 320, 512, 768, 768, 512, 512,
      0, 0, 0, 0, 0, 1, 1, bspan);
  // 2) scoring = leaky(x @ Wscore + bscore) [320,256], K=768
  gemm6<160, 128, 2><<<dim3(2, 2, 1), 320, SM_160_128>>>(
      x, Wscore, d_scoring, 320, 256, 768, 768, 256, 256,
      0, 0, 0, 0, 0, 1, 1, bscore);
  // 3) transposes for inPT / xtailPT
  k_prep2<<<(2 * BATCH * HP * L + 255) / 256, 256>>>();
  // 4) U[(b,r)] = h_tail[b] @ Wtri[r][0:128] + Wtri[r][128]; z=(b,r), ZD=R
  gemm6<160, 128, 2><<<dim3(129, 1, BATCH * R), 320, SM_160_128>>>(
      d_hidden + 2 * H, Wtri, d_U, L, NKJ, H, 4 * H, NKJ, NKJ,
      (long long)L * (4 * H), 0, 0, WTRI_R, (long long)L * NKJ,
      R, 2, nullptr);
  // 5) G[b] = x_head[b] @ Wfin[0:128] + Wfin[128]; z=b
  gemm6<160, 128, 2><<<dim3(129, 1, BATCH), 320, SM_160_128>>>(
      d_scoring, Wfin, d_G, L, NKJ, H, 2 * H, NKJ, NKJ,
      (long long)L * (2 * H), 0, 0, 0, (long long)L * NKJ,
      1, 2, nullptr);
  // 6) Gt2[b] = G[b][:, 0:128] @ xtailPT[b][0:128] + G[..][128]; z=b
  gemm6<128, 160, 2><<<dim3(1, 160, BATCH), 320, SM_128_160>>>(
      d_G, d_xtailPT, d_Gt2, L * H, L, H, HP, L, L,
      (long long)L * NKJ, 0, (long long)HP * L, 0, (long long)(L * H) * L,
      1, 3, nullptr);
  // 6b) Gt3[b][y][xq] = transpose(Gt2)
  k_transpose<<<dim3(640, 5, 2), dim3(32, 8)>>>(d_Gt2, d_Gt3);
  // 7) W2[z] = U[z][:, 0:128] @ inPT[b][0:128] + U[z][:, 128]; z=(b,(r,y))
  gemm6<128, 160, 2><<<dim3(1, 1, BATCH * R * L), 320, SM_128_160>>>(
      d_U, d_inPT, d_W2, H, L, H, HP, L, L,
      (long long)R * L * NKJ, NKJ, (long long)HP * L, 0, (long long)H * L,
      R * L, 3, nullptr);
  // 10) HRW[b] = h_in_repr[b] [160,128] @ Wmlp [128,128]; z=b
  gemm6<160, 128, 2><<<dim3(1, 1, BATCH), 320, SM_160_128>>>(
      d_hidden, Wmlp, d_HRW, L, H, H, 4 * H, H, H,
      (long long)L * (4 * H), 0, 0, 0, (long long)L * H,
      1, 0, nullptr);
  // 8+9+11) fused logits -> softmax -> SP -> score (alpha never hits HBM)
  k_fused8<<<dim3(1, 2, BATCH * R * L), 200, SM_F8>>>(
      d_hidden + H, d_W2, d_HRW, d_Gt3, bmlp, out);
}